// round 14
// baseline (speedup 1.0000x reference)
#include <cuda_runtime.h>
#include <cuda_bf16.h>
#include <cuda_fp16.h>

#define BATCH 16
#define NN    1024
#define DD    64
#define EPSF      0.1f
#define INV_EPS   10.0f
#define LOG_MU   (-6.9314616f)   // log(1/1024 + 1e-8)
#define THRESH    0.1f
#define MAX_ITER  100
#define GB        128            // flat persistent grid: 128 blocks <= 148 SMs, co-resident
#define TB        1024

// ---------------- device scratch (static: no allocations allowed) ----------------
__device__ unsigned char g_K8[BATCH * NN * NN];  // 16 MB: K = exp(-C/eps), e4m3
__device__ __nv_bfloat16 g_xsh[BATCH * NN * DD]; // softmaxed x, bf16 (exact tf32 subset)
__device__ __nv_bfloat16 g_ysh[BATCH * NN * DD]; // softmaxed y, bf16
__device__ float g_x2[BATCH * NN];
__device__ float g_y2[BATCH * NN];
__device__ float g_u [BATCH * NN];
__device__ float g_v [BATCH * NN];
__device__ float g_a [BATCH * NN];        // exp(u/eps)
__device__ float g_b [BATCH * NN];        // exp(v/eps)
__device__ float g_errA[MAX_ITER * BATCH];
__device__ double   g_cost;
__device__ unsigned g_bar_cnt;
__device__ unsigned g_bar_gen;

// ---------------- software grid barrier (all GB blocks co-resident) ----------------
__device__ __forceinline__ void grid_barrier() {
    __threadfence();
    __syncthreads();
    if (threadIdx.x == 0) {
        unsigned gen = *((volatile unsigned*)&g_bar_gen);
        if (atomicAdd(&g_bar_cnt, 1u) == GB - 1u) {
            g_bar_cnt = 0u;
            __threadfence();
            *((volatile unsigned*)&g_bar_gen) = gen + 1u;
        } else {
            while (*((volatile unsigned*)&g_bar_gen) == gen) { __nanosleep(64); }
        }
    }
    __syncthreads();
}

// 4 e4m3 bytes (one 32-bit word) -> 4 floats (exact via f16)
__device__ __forceinline__ float4 cvt_e4m3x4(unsigned wv) {
    unsigned h0, h1;
    asm("{.reg .b16 lo, hi;\n\t"
        "mov.b32 {lo, hi}, %2;\n\t"
        "cvt.rn.f16x2.e4m3x2 %0, lo;\n\t"
        "cvt.rn.f16x2.e4m3x2 %1, hi;}\n\t"
        : "=r"(h0), "=r"(h1) : "r"(wv));
    float2 fa = __half22float2(*(__half2*)&h0);
    float2 fb = __half22float2(*(__half2*)&h1);
    return make_float4(fa.x, fa.y, fb.x, fb.y);
}

// pack 2 floats -> e4m3x2 (lo = first memory byte)
__device__ __forceinline__ unsigned short pack_e4m3x2(float lo, float hi) {
    unsigned short r;
    asm("cvt.rn.satfinite.e4m3x2.f32 %0, %1, %2;" : "=h"(r) : "f"(hi), "f"(lo));
    return r;
}

// dot of 16 fp8 (one uint4) with 16 floats (four float4)
__device__ __forceinline__ float dot16(uint4 q, float4 b0, float4 b1, float4 b2, float4 b3) {
    float4 f0 = cvt_e4m3x4(q.x);
    float4 f1 = cvt_e4m3x4(q.y);
    float4 f2 = cvt_e4m3x4(q.z);
    float4 f3 = cvt_e4m3x4(q.w);
    float s = f0.x*b0.x + f0.y*b0.y + f0.z*b0.z + f0.w*b0.w;
    s += f1.x*b1.x + f1.y*b1.y + f1.z*b1.z + f1.w*b1.w;
    s += f2.x*b2.x + f2.y*b2.y + f2.z*b2.z + f2.w*b2.w;
    s += f3.x*b3.x + f3.y*b3.y + f3.z*b3.z + f3.w*b3.w;
    return s;
}

// sum of k*b*ln(k) over 16 fp8 k's (log guarded: k==0 contributes 0)
__device__ __forceinline__ float dot16log(uint4 q, float4 b0, float4 b1, float4 b2, float4 b3) {
    float4 f0 = cvt_e4m3x4(q.x);
    float4 f1 = cvt_e4m3x4(q.y);
    float4 f2 = cvt_e4m3x4(q.z);
    float4 f3 = cvt_e4m3x4(q.w);
    float s = 0.f;
    s += f0.x*b0.x*__logf(fmaxf(f0.x,1e-20f)) + f0.y*b0.y*__logf(fmaxf(f0.y,1e-20f));
    s += f0.z*b0.z*__logf(fmaxf(f0.z,1e-20f)) + f0.w*b0.w*__logf(fmaxf(f0.w,1e-20f));
    s += f1.x*b1.x*__logf(fmaxf(f1.x,1e-20f)) + f1.y*b1.y*__logf(fmaxf(f1.y,1e-20f));
    s += f1.z*b1.z*__logf(fmaxf(f1.z,1e-20f)) + f1.w*b1.w*__logf(fmaxf(f1.w,1e-20f));
    s += f2.x*b2.x*__logf(fmaxf(f2.x,1e-20f)) + f2.y*b2.y*__logf(fmaxf(f2.y,1e-20f));
    s += f2.z*b2.z*__logf(fmaxf(f2.z,1e-20f)) + f2.w*b2.w*__logf(fmaxf(f2.w,1e-20f));
    s += f3.x*b3.x*__logf(fmaxf(f3.x,1e-20f)) + f3.y*b3.y*__logf(fmaxf(f3.y,1e-20f));
    s += f3.z*b3.z*__logf(fmaxf(f3.z,1e-20f)) + f3.w*b3.w*__logf(fmaxf(f3.w,1e-20f));
    return s;
}

// ---------------- softmax (D=64): 2 rows/warp, float4 loads, bf16 stores + init ----------------
__global__ void softmax_kernel(const float* __restrict__ x, const float* __restrict__ y) {
    int gidx = blockIdx.x * blockDim.x + threadIdx.x;
    if (gidx < BATCH * NN) { g_u[gidx] = 0.f; g_v[gidx] = 0.f; g_a[gidx] = 1.f; g_b[gidx] = 1.f; }
    if (gidx < MAX_ITER * BATCH) g_errA[gidx] = 0.f;
    if (gidx == 0) { g_cost = 0.0; g_bar_cnt = 0u; g_bar_gen = 0u; }

    int gwarp = gidx >> 5;
    int lane  = threadIdx.x & 31;
    int half  = lane >> 4;
    int hl    = lane & 15;
    int row2  = gwarp * 2 + half;
    const float* src; __nv_bfloat16* dst; float* nrm; int row;
    if (row2 < BATCH * NN) { src = x; dst = g_xsh; nrm = g_x2; row = row2; }
    else                   { src = y; dst = g_ysh; nrm = g_y2; row = row2 - BATCH * NN; }

    float4 e = ((const float4*)(src + (size_t)row * DD))[hl];
    float m = fmaxf(fmaxf(e.x, e.y), fmaxf(e.z, e.w));
    #pragma unroll
    for (int o = 8; o; o >>= 1) m = fmaxf(m, __shfl_xor_sync(0xFFFFFFFFu, m, o));
    float s0 = __expf(e.x - m), s1 = __expf(e.y - m);
    float s2 = __expf(e.z - m), s3 = __expf(e.w - m);
    float s = (s0 + s1) + (s2 + s3);
    #pragma unroll
    for (int o = 8; o; o >>= 1) s += __shfl_xor_sync(0xFFFFFFFFu, s, o);
    float inv = 1.0f / s;
    float p0 = s0 * inv, p1 = s1 * inv, p2 = s2 * inv, p3 = s3 * inv;
    __nv_bfloat162 h0 = __floats2bfloat162_rn(p0, p1);
    __nv_bfloat162 h1 = __floats2bfloat162_rn(p2, p3);
    uint2 pk; pk.x = *(unsigned*)&h0; pk.y = *(unsigned*)&h1;
    *(uint2*)(dst + (size_t)row * DD + hl * 4) = pk;
    float q = (p0 * p0 + p1 * p1) + (p2 * p2 + p3 * p3);
    #pragma unroll
    for (int o = 8; o; o >>= 1) q += __shfl_xor_sync(0xFFFFFFFFu, q, o);
    if (hl == 0) nrm[row] = q;
}

// ---------------- K = exp((2 x.y - |x|^2 - |y|^2)/eps) via tf32 MMA, e4m3 store ----------------
#define XS_STRIDE 68   // (row*68+col)%32 = (row*4+col)%32 -> conflict-free fragment LDS
__global__ void __launch_bounds__(256) buildK_mma() {
    __shared__ float xs[64 * XS_STRIDE];
    __shared__ float ys[64 * XS_STRIDE];
    __shared__ float x2s[64], y2s[64];

    int bx = blockIdx.x;
    int batch = bx >> 8;          // 256 tiles per batch (16 i-tiles x 16 j-tiles)
    int tile  = bx & 255;
    int i0 = (tile >> 4) * 64, j0 = (tile & 15) * 64;
    int t = threadIdx.x;

    const uint4* xsrc = (const uint4*)(g_xsh + (size_t)(batch * NN + i0) * DD);
    const uint4* ysrc = (const uint4*)(g_ysh + (size_t)(batch * NN + j0) * DD);
    #pragma unroll
    for (int k = 0; k < 2; k++) {
        int lin = k * 256 + t;
        int row = lin >> 3, c = (lin & 7) * 8;
        uint4 qx = xsrc[lin];
        uint4 qy = ysrc[lin];
        float2 x0 = __bfloat1622float2(*(const __nv_bfloat162*)&qx.x);
        float2 x1 = __bfloat1622float2(*(const __nv_bfloat162*)&qx.y);
        float2 x2v = __bfloat1622float2(*(const __nv_bfloat162*)&qx.z);
        float2 x3 = __bfloat1622float2(*(const __nv_bfloat162*)&qx.w);
        float2 y0 = __bfloat1622float2(*(const __nv_bfloat162*)&qy.x);
        float2 y1 = __bfloat1622float2(*(const __nv_bfloat162*)&qy.y);
        float2 y2v = __bfloat1622float2(*(const __nv_bfloat162*)&qy.z);
        float2 y3 = __bfloat1622float2(*(const __nv_bfloat162*)&qy.w);
        float* xd = xs + row * XS_STRIDE + c;
        float* yd = ys + row * XS_STRIDE + c;
        *((float4*)(xd    )) = make_float4(x0.x, x0.y, x1.x, x1.y);
        *((float4*)(xd + 4)) = make_float4(x2v.x, x2v.y, x3.x, x3.y);
        *((float4*)(yd    )) = make_float4(y0.x, y0.y, y1.x, y1.y);
        *((float4*)(yd + 4)) = make_float4(y2v.x, y2v.y, y3.x, y3.y);
    }
    if (t < 64)            x2s[t]      = g_x2[batch * NN + i0 + t];
    else if (t < 128)      y2s[t - 64] = g_y2[batch * NN + j0 + (t - 64)];
    __syncthreads();

    int w = t >> 5, lane = t & 31;
    int mo = (w >> 1) * 16;
    int no = (w & 1) * 32;
    int gr = lane >> 2, gc = lane & 3;

    float acc[4][4];
    #pragma unroll
    for (int nt = 0; nt < 4; nt++)
        #pragma unroll
        for (int q = 0; q < 4; q++) acc[nt][q] = 0.f;

    #pragma unroll
    for (int k0 = 0; k0 < 64; k0 += 8) {
        unsigned a0, a1, a2, a3;
        {
            const float* base = xs + (mo + gr) * XS_STRIDE + k0 + gc;
            a0 = __float_as_uint(base[0]);
            a1 = __float_as_uint(base[8 * XS_STRIDE]);
            a2 = __float_as_uint(base[4]);
            a3 = __float_as_uint(base[8 * XS_STRIDE + 4]);
        }
        #pragma unroll
        for (int nt = 0; nt < 4; nt++) {
            const float* bb = ys + (no + nt * 8 + gr) * XS_STRIDE + k0 + gc;
            unsigned b0 = __float_as_uint(bb[0]);
            unsigned b1 = __float_as_uint(bb[4]);
            asm volatile(
                "mma.sync.aligned.m16n8k8.row.col.f32.tf32.tf32.f32 "
                "{%0,%1,%2,%3}, {%4,%5,%6,%7}, {%8,%9}, {%0,%1,%2,%3};"
                : "+f"(acc[nt][0]), "+f"(acc[nt][1]), "+f"(acc[nt][2]), "+f"(acc[nt][3])
                : "r"(a0), "r"(a1), "r"(a2), "r"(a3), "r"(b0), "r"(b1));
        }
    }

    unsigned char* Kb = g_K8 + (size_t)batch * NN * NN;
    float xi0 = x2s[mo + gr], xi1 = x2s[mo + gr + 8];
    int r0 = i0 + mo + gr, r1 = r0 + 8;
    #pragma unroll
    for (int nt = 0; nt < 4; nt++) {
        int jc = j0 + no + nt * 8 + gc * 2;
        float yj0 = y2s[no + nt * 8 + gc * 2];
        float yj1 = y2s[no + nt * 8 + gc * 2 + 1];
        float k00 = __expf((2.0f * acc[nt][0] - xi0 - yj0) * INV_EPS);
        float k01 = __expf((2.0f * acc[nt][1] - xi0 - yj1) * INV_EPS);
        float k10 = __expf((2.0f * acc[nt][2] - xi1 - yj0) * INV_EPS);
        float k11 = __expf((2.0f * acc[nt][3] - xi1 - yj1) * INV_EPS);
        *(unsigned short*)(Kb + (size_t)r0 * NN + jc) = pack_e4m3x2(k00, k01);
        *(unsigned short*)(Kb + (size_t)r1 * NN + jc) = pack_e4m3x2(k10, k11);
    }
}

// ---------------- persistent Sinkhorn loop + cost + finalize (fp8 K) ----------------
// Block bk: batch = bk>>3, seg = bk&7.
__global__ void __launch_bounds__(TB, 1) sinkhorn_persistent(float* __restrict__ out) {
    int bk  = blockIdx.x;
    int tid = threadIdx.x;
    int batch = bk >> 3;
    int seg   = bk & 7;
    int w = tid >> 5, lane = tid & 31;

    __shared__ float4 vec4[256];        // b (row/cost phases) or a (col phase), fp32
    __shared__ float  rsum[128];
    __shared__ float4 psum4[1024];      // col-phase partials (16 KB)
    __shared__ int    s_done;
    float* vecs = (float*)vec4;
    float* psum = (float*)psum4;

    int it = 0;
    for (; it < MAX_ITER; ++it) {
        // ======== row phase: r_i = sum_j K_ij b_j ; update u, a ========
        if (tid < 256) vec4[tid] = ((const float4*)(g_b + batch * NN))[tid];
        __syncthreads();
        {
            int ibase = seg * 128 + w * 4;      // 4 consecutive rows per warp
            const uint4* K0 = (const uint4*)(g_K8 + (size_t)(batch * NN + ibase) * NN);
            float s0 = 0.f, s1 = 0.f, s2 = 0.f, s3 = 0.f;
            #pragma unroll
            for (int k = 0; k < 2; k++) {
                int idx = k * 32 + lane;        // uint4 index within row (16 fp8 each)
                float4 b0 = vec4[idx * 4], b1 = vec4[idx * 4 + 1];
                float4 b2 = vec4[idx * 4 + 2], b3 = vec4[idx * 4 + 3];
                s0 += dot16(K0[          idx], b0, b1, b2, b3);
                s1 += dot16(K0[ 64 +     idx], b0, b1, b2, b3);
                s2 += dot16(K0[128 +     idx], b0, b1, b2, b3);
                s3 += dot16(K0[192 +     idx], b0, b1, b2, b3);
            }
            #pragma unroll
            for (int o = 16; o; o >>= 1) {
                s0 += __shfl_xor_sync(0xFFFFFFFFu, s0, o);
                s1 += __shfl_xor_sync(0xFFFFFFFFu, s1, o);
                s2 += __shfl_xor_sync(0xFFFFFFFFu, s2, o);
                s3 += __shfl_xor_sync(0xFFFFFFFFu, s3, o);
            }
            if (lane == 0) {
                rsum[w * 4 + 0] = s0; rsum[w * 4 + 1] = s1;
                rsum[w * 4 + 2] = s2; rsum[w * 4 + 3] = s3;
            }
        }
        __syncthreads();
        if (tid < 128) {
            int gi = batch * NN + seg * 128 + tid;
            float uo = g_u[gi];
            float a  = g_a[gi];
            float lse = logf(fmaf(a, rsum[tid], 1e-6f));   // accurate log: iteration fidelity
            float un  = EPSF * (LOG_MU - lse) + uo;
            g_u[gi] = un;
            g_a[gi] = expf(un * INV_EPS);
            psum[tid] = fabsf(un - uo);
        }
        __syncthreads();
        if (tid < 32) {                 // warp-reduced derr
            float d = psum[tid] + psum[tid + 32] + psum[tid + 64] + psum[tid + 96];
            #pragma unroll
            for (int o = 16; o; o >>= 1) d += __shfl_xor_sync(0xFFFFFFFFu, d, o);
            if (tid == 0) atomicAdd(&g_errA[it * BATCH + batch], d);
        }
        grid_barrier();   // new a visible everywhere; err slot complete

        // ======== col phase: s_j = sum_i K_ij a_i ; update v, b ========
        if (tid < 256) vec4[tid] = ((const float4*)(g_a + batch * NN))[tid];
        __syncthreads();
        {
            int tx = tid & 31;          // 4 cols each (32 x 4 = 128)
            int ig = tid >> 5;          // 32 i-groups of 32 rows
            const unsigned char* Kc = g_K8 + (size_t)(batch * NN + ig * 32) * NN
                                      + seg * 128 + tx * 4;
            const float* as = vecs + ig * 32;
            float a0 = 0.f, a1 = 0.f, a2 = 0.f, a3 = 0.f;
            #pragma unroll 8
            for (int i = 0; i < 32; i++) {
                unsigned wv = *(const unsigned*)(Kc + (size_t)i * NN);
                float av = as[i];
                float4 f = cvt_e4m3x4(wv);
                a0 = fmaf(av, f.x, a0); a1 = fmaf(av, f.y, a1);
                a2 = fmaf(av, f.z, a2); a3 = fmaf(av, f.w, a3);
            }
            psum4[ig * 32 + tx] = make_float4(a0, a1, a2, a3);
        }
        __syncthreads();
        if (tid < 128) {
            float s = 0.f;
            #pragma unroll
            for (int ig = 0; ig < 32; ig++)
                s += ((const float*)&psum4[ig * 32 + (tid >> 2)])[tid & 3];
            int gj = batch * NN + seg * 128 + tid;
            float vo = g_v[gj], b = g_b[gj];
            float vn = EPSF * (LOG_MU - logf(fmaf(b, s, 1e-6f))) + vo;
            g_v[gj] = vn;
            g_b[gj] = expf(vn * INV_EPS);
        }
        grid_barrier();   // new b visible; safe to read err and proceed

        // ======== convergence check (identical on every block) ========
        if (tid == 0) {
            float e = 0.f;
            #pragma unroll
            for (int bb = 0; bb < BATCH; bb++) e += g_errA[it * BATCH + bb];
            s_done = (e * (1.0f / BATCH) < THRESH) ? 1 : 0;
        }
        __syncthreads();
        if (s_done) break;
    }

    // ======== cost phase: -eps * sum_ij a_i b_j K_ij ln K_ij ========
    if (tid < 256) vec4[tid] = ((const float4*)(g_b + batch * NN))[tid];
    __syncthreads();
    {
        int ibase = seg * 128 + w * 4;
        const uint4* K0 = (const uint4*)(g_K8 + (size_t)(batch * NN + ibase) * NN);
        float s0 = 0.f, s1 = 0.f, s2 = 0.f, s3 = 0.f;
        #pragma unroll
        for (int k = 0; k < 2; k++) {
            int idx = k * 32 + lane;
            float4 b0 = vec4[idx * 4], b1 = vec4[idx * 4 + 1];
            float4 b2 = vec4[idx * 4 + 2], b3 = vec4[idx * 4 + 3];
            s0 += dot16log(K0[          idx], b0, b1, b2, b3);
            s1 += dot16log(K0[ 64 +     idx], b0, b1, b2, b3);
            s2 += dot16log(K0[128 +     idx], b0, b1, b2, b3);
            s3 += dot16log(K0[192 +     idx], b0, b1, b2, b3);
        }
        #pragma unroll
        for (int o = 16; o; o >>= 1) {
            s0 += __shfl_xor_sync(0xFFFFFFFFu, s0, o);
            s1 += __shfl_xor_sync(0xFFFFFFFFu, s1, o);
            s2 += __shfl_xor_sync(0xFFFFFFFFu, s2, o);
            s3 += __shfl_xor_sync(0xFFFFFFFFu, s3, o);
        }
        if (lane == 0) {
            rsum[w * 4 + 0] = s0; rsum[w * 4 + 1] = s1;
            rsum[w * 4 + 2] = s2; rsum[w * 4 + 3] = s3;
        }
    }
    __syncthreads();
    if (tid < 128) {
        int gi = batch * NN + seg * 128 + tid;
        psum[tid] = g_a[gi] * rsum[tid];
    }
    __syncthreads();
    if (tid == 0) {
        float bsum = 0.f;
        #pragma unroll
        for (int k = 0; k < 128; k++) bsum += psum[k];
        atomicAdd(&g_cost, (double)(-EPSF * bsum));
    }
    grid_barrier();
    if (bk == 0 && tid == 0) out[0] = (float)(g_cost * (1.0 / (double)BATCH));
}

// ---------------- launch ----------------
extern "C" void kernel_launch(void* const* d_in, const int* in_sizes, int n_in,
                              void* d_out, int out_size) {
    const float* x = (const float*)d_in[0];
    const float* y = (const float*)d_in[1];
    float* out = (float*)d_out;
    (void)in_sizes; (void)n_in; (void)out_size;

    softmax_kernel<<<2048, 256>>>(x, y);   // 2 rows/warp softmax + init, bf16 stores
    buildK_mma<<<4096, 256>>>();           // bf16 panels -> tf32 HMMA -> e4m3 K
    sinkhorn_persistent<<<GB, TB>>>(out);  // persistent loop + cost + finalize (fp8 K)
}